// round 1
// baseline (speedup 1.0000x reference)
#include <cuda_runtime.h>
#include <cstdint>

// ============================================================================
// Quantizing_12060268167756: VQ codebook lookup
//   x:      (8, 2048, 512) f32  -> N = 16384 rows, E = 512
//   weight: (8192, 512)    f32  -> Q = 8192 codewords
//   out:    q_data (N, E) f32, then q_idx (N,) cast to f32 (if out_size fits)
//
// dist[n,q] = fl( fl( x_sq[n] - 2*dot[n,q] ) + w_sq[q] )   (mimics reference
// elementwise rounding; 2*dot is exact so FMA contraction is safe)
// argmin with first-index tie-break (jnp.argmin semantics).
// ============================================================================

#define E    512
#define NMAX 16384
#define QMAX 8192

__device__ float g_xsq[NMAX];
__device__ float g_wsq[QMAX];
__device__ int   g_idx[NMAX];

// ---------------------------------------------------------------------------
// Row sum-of-squares, fp64 accumulate -> correctly-rounded fp32.
// One warp per row; 8 rows per 256-thread block.
// ---------------------------------------------------------------------------
__global__ void __launch_bounds__(256) rowsq_x_kernel(const float* __restrict__ X, int N)
{
    int row = blockIdx.x * 8 + (threadIdx.x >> 5);
    if (row >= N) return;
    int lane = threadIdx.x & 31;
    const float* p = X + (size_t)row * E;
    double s = 0.0;
    #pragma unroll
    for (int c = lane; c < E; c += 32) { float v = p[c]; s += (double)v * (double)v; }
    #pragma unroll
    for (int o = 16; o > 0; o >>= 1) s += __shfl_down_sync(0xffffffffu, s, o);
    if (lane == 0) g_xsq[row] = (float)s;
}

__global__ void __launch_bounds__(256) rowsq_w_kernel(const float* __restrict__ W, int Q)
{
    int row = blockIdx.x * 8 + (threadIdx.x >> 5);
    if (row >= Q) return;
    int lane = threadIdx.x & 31;
    const float* p = W + (size_t)row * E;
    double s = 0.0;
    #pragma unroll
    for (int c = lane; c < E; c += 32) { float v = p[c]; s += (double)v * (double)v; }
    #pragma unroll
    for (int o = 16; o > 0; o >>= 1) s += __shfl_down_sync(0xffffffffu, s, o);
    if (lane == 0) g_wsq[row] = (float)s;
}

// ---------------------------------------------------------------------------
// Fused GEMM + argmin.
//   Tile: BM=128 rows (x) x BN=128 cols (codewords), BK=16.
//   256 threads (16x16), 8x8 micro-tile per thread with split-half float4
//   mapping (rows {ty*4..+3, 64+ty*4..+3}, cols {tx*4..+3, 64+tx*4..+3})
//   for conflict-free LDS.128.
//   Per-thread running (min dist, idx) across all q-tiles; smem reduction.
// ---------------------------------------------------------------------------
#define BM 128
#define BN 128
#define BK 16

__global__ void __launch_bounds__(256) vq_kernel(const float* __restrict__ X,
                                                 const float* __restrict__ W,
                                                 int N, int Q)
{
    __shared__ float As[BK][BM];
    __shared__ float Bs[BK][BN];
    __shared__ float sd[BM][17];
    __shared__ int   si[BM][17];

    const int tid = threadIdx.x;
    const int tx  = tid & 15;
    const int ty  = tid >> 4;
    const int rowBase = blockIdx.x * BM;

    int rown[8];
    #pragma unroll
    for (int i = 0; i < 4; i++) { rown[i] = ty * 4 + i; rown[i + 4] = 64 + ty * 4 + i; }

    float myxsq[8];
    #pragma unroll
    for (int i = 0; i < 8; i++) myxsq[i] = g_xsq[rowBase + rown[i]];

    float bestd[8];
    int   besti[8];
    #pragma unroll
    for (int i = 0; i < 8; i++) { bestd[i] = __int_as_float(0x7f800000); besti[i] = 0; }

    for (int qBase = 0; qBase < Q; qBase += BN) {
        float acc[8][8];
        #pragma unroll
        for (int i = 0; i < 8; i++)
            #pragma unroll
            for (int j = 0; j < 8; j++) acc[i][j] = 0.0f;

        for (int k0 = 0; k0 < E; k0 += BK) {
            __syncthreads();
            // Load 128x16 tiles of X and W (512 float4 each; 2 per thread).
            #pragma unroll
            for (int l = 0; l < 2; l++) {
                int f4 = tid + l * 256;
                int r  = f4 >> 2;
                int c  = (f4 & 3) << 2;
                float4 v = *reinterpret_cast<const float4*>(X + (size_t)(rowBase + r) * E + k0 + c);
                As[c + 0][r] = v.x; As[c + 1][r] = v.y; As[c + 2][r] = v.z; As[c + 3][r] = v.w;
                float4 u = *reinterpret_cast<const float4*>(W + (size_t)(qBase + r) * E + k0 + c);
                Bs[c + 0][r] = u.x; Bs[c + 1][r] = u.y; Bs[c + 2][r] = u.z; Bs[c + 3][r] = u.w;
            }
            __syncthreads();
            #pragma unroll
            for (int k = 0; k < BK; k++) {
                float4 a0 = *reinterpret_cast<const float4*>(&As[k][ty * 4]);
                float4 a1 = *reinterpret_cast<const float4*>(&As[k][64 + ty * 4]);
                float4 b0 = *reinterpret_cast<const float4*>(&Bs[k][tx * 4]);
                float4 b1 = *reinterpret_cast<const float4*>(&Bs[k][64 + tx * 4]);
                float a[8] = {a0.x, a0.y, a0.z, a0.w, a1.x, a1.y, a1.z, a1.w};
                float b[8] = {b0.x, b0.y, b0.z, b0.w, b1.x, b1.y, b1.z, b1.w};
                #pragma unroll
                for (int i = 0; i < 8; i++)
                    #pragma unroll
                    for (int j = 0; j < 8; j++)
                        acc[i][j] = fmaf(a[i], b[j], acc[i][j]);
            }
        }

        // Fold this q-tile into the running argmin. j ascends in q within the
        // thread, so strict '<' keeps the first (lowest-q) minimum.
        #pragma unroll
        for (int j = 0; j < 8; j++) {
            int q = qBase + ((j < 4) ? (tx * 4 + j) : (64 + tx * 4 + (j - 4)));
            float wq = g_wsq[q];
            #pragma unroll
            for (int i = 0; i < 8; i++) {
                float t = myxsq[i] - 2.0f * acc[i][j];  // 2*acc exact; FMA-safe
                float d = t + wq;                        // second rounding, as ref
                if (d < bestd[i]) { bestd[i] = d; besti[i] = q; }
            }
        }
    }

    // Cross-thread reduction: 16 candidates (tx) per row; lexicographic
    // (dist, idx) so the global first-occurrence minimum wins.
    __syncthreads();
    #pragma unroll
    for (int i = 0; i < 8; i++) { sd[rown[i]][tx] = bestd[i]; si[rown[i]][tx] = besti[i]; }
    __syncthreads();
    if (tid < BM) {
        float bd = sd[tid][0]; int bi = si[tid][0];
        #pragma unroll
        for (int t = 1; t < 16; t++) {
            float d = sd[tid][t]; int ii = si[tid][t];
            if (d < bd || (d == bd && ii < bi)) { bd = d; bi = ii; }
        }
        g_idx[rowBase + tid] = bi;
    }
}

// ---------------------------------------------------------------------------
// Gather: out_data[n,:] = weight[idx[n],:]; out_idx[n] = (float)idx[n].
// One 128-thread CTA per row (128 x float4 = 512 floats).
// ---------------------------------------------------------------------------
__global__ void __launch_bounds__(128) gather_kernel(const float* __restrict__ W,
                                                     float* __restrict__ outData,
                                                     float* __restrict__ outIdxF,
                                                     int writeIdx)
{
    int n = blockIdx.x;
    int q = g_idx[n];
    float4 v = reinterpret_cast<const float4*>(W + (size_t)q * E)[threadIdx.x];
    reinterpret_cast<float4*>(outData + (size_t)n * E)[threadIdx.x] = v;
    if (writeIdx && threadIdx.x == 0) outIdxF[n] = (float)q;
}

// ---------------------------------------------------------------------------
extern "C" void kernel_launch(void* const* d_in, const int* in_sizes, int n_in,
                              void* d_out, int out_size)
{
    const float* X = (const float*)d_in[0];
    const float* W = (const float*)d_in[1];
    int N = in_sizes[0] / E;
    int Q = in_sizes[1] / E;
    if (N <= 0 || Q <= 0 || N > NMAX || Q > QMAX) return;

    float* out = (float*)d_out;

    rowsq_x_kernel<<<(N + 7) / 8, 256>>>(X, N);
    rowsq_w_kernel<<<(Q + 7) / 8, 256>>>(W, Q);
    vq_kernel<<<N / BM, 256>>>(X, W, N, Q);

    // Output layout: q_data (N*E) followed by q_idx (N) if out_size has room.
    int writeIdx = (out_size >= N * E + N) ? 1 : 0;
    gather_kernel<<<N, 128>>>(W, out, out + (size_t)N * E, writeIdx);
}